// round 11
// baseline (speedup 1.0000x reference)
#include <cuda_runtime.h>
#include <cuda_bf16.h>
#include <cstdint>

typedef unsigned long long ull;
typedef unsigned int uint;

#define N_BATCH 64
#define T_SEQ   2000
#define DQ      256
#define NTOK    10
#define NJ      80
#define NJT     10
#define TILE    64
#define NC      8            // 4 tiles x 2 k-chunks
#define THREADS 256
#define SCALE_LG 0.17677669529663687f
#define OUT_ELEMS (N_BATCH * T_SEQ * DQ)

// ---- smem (80,896 B/CTA -> 2 CTAs/SM) ----
#define XSTR   68            // uint2 per X row (544 B)
#define XBYTES 34816
#define OFF_X1 34816
#define OFF_VH 69632         // vhp: ull[5*256] = 10240 B
#define OFF_IDX 79872
#define SMEM_BYTES 80896
#define SLSTR  86            // sLog row stride (aliases X buf1)

__device__ uint4 g_Bf[NJT * 16 * 32];   // Wqk bf16 hi/lo in MMA fragment order
__device__ ull   g_vhp[5 * 256];        // vh k-pairs interleaved
__device__ int   g_idx_is64;

// ---------- helpers ----------
__device__ __forceinline__ void fma2(ull& acc, ull a, ull b) {
    asm("fma.rn.f32x2 %0, %1, %2, %0;" : "+l"(acc) : "l"(a), "l"(b));
}
__device__ __forceinline__ float2 u2f2(ull v) {
    float2 r; asm("mov.b64 {%0, %1}, %2;" : "=f"(r.x), "=f"(r.y) : "l"(v)); return r;
}
__device__ __forceinline__ ull mk2(float lo, float hi) {
    ull r; asm("mov.b64 %0, {%1, %2};" : "=l"(r) : "f"(lo), "f"(hi)); return r;
}
__device__ __forceinline__ uint packbf(float x0, float x1) {
    uint r; asm("cvt.rn.bf16x2.f32 %0, %1, %2;" : "=r"(r) : "f"(x1), "f"(x0)); return r;
}
__device__ __forceinline__ float2 bf2f(uint u) {
    __nv_bfloat162 h = *reinterpret_cast<__nv_bfloat162*>(&u);
    return __bfloat1622float2(h);
}
__device__ __forceinline__ void mma16816(float* c,
    uint a0, uint a1, uint a2, uint a3, uint b0, uint b1) {
    asm volatile("mma.sync.aligned.m16n8k16.row.col.f32.bf16.bf16.f32 "
        "{%0,%1,%2,%3}, {%4,%5,%6,%7}, {%8,%9}, {%0,%1,%2,%3};"
        : "+f"(c[0]), "+f"(c[1]), "+f"(c[2]), "+f"(c[3])
        : "r"(a0), "r"(a1), "r"(a2), "r"(a3), "r"(b0), "r"(b1));
}

// =====================================================================
// Precompute (unchanged): Wqk -> fragment-order bf16 hi/lo; vhp pairs.
// =====================================================================
__global__ void precompute_kernel(const float* __restrict__ embed,
                                  const float* __restrict__ Wq,
                                  const float* __restrict__ Wk,
                                  const float* __restrict__ Wv,
                                  const int*   __restrict__ pidx) {
    __shared__ float skeys[NTOK * 32];
    const int tid = threadIdx.x;
    for (int e = tid; e < NTOK * 32; e += 256) skeys[e] = tanhf(embed[e]);
    __syncthreads();

    const int b = blockIdx.x;
    if (b < NJ) {
        const int h = b / NTOK, k = b % NTOK;
        __shared__ float skm[32];
        if (tid < 32) {
            float s = 0.f;
            #pragma unroll
            for (int d = 0; d < 32; ++d) s += skeys[k * 32 + d] * Wk[(h * 32 + tid) * 32 + d];
            skm[tid] = s;
        }
        __syncthreads();
        if (tid < 128) {
            const int c0 = 2 * tid;
            float s0 = 0.f, s1 = 0.f;
            #pragma unroll
            for (int d = 0; d < 32; ++d) {
                const float km = skm[d];
                s0 += km * Wq[(h * 32 + d) * DQ + c0];
                s1 += km * Wq[(h * 32 + d) * DQ + c0 + 1];
            }
            s0 *= SCALE_LG; s1 *= SCALE_LG;
            const uint hi = packbf(s0, s1);
            const float2 f = bf2f(hi);
            const uint lo = packbf(s0 - f.x, s1 - f.y);
            const int j = b >> 3, gr = b & 7;
            const int gk = tid >> 3, qq = tid & 7;
            const int q = qq & 3, hf = qq >> 2;
            uint* dst = (uint*)&g_Bf[(j * 16 + gk) * 32 + gr * 4 + q];
            dst[hf * 2]     = hi;
            dst[hf * 2 + 1] = lo;
        }
    } else {
        __shared__ float svh[NTOK * 256];
        for (int e = tid; e < NTOK * DQ; e += 256) {
            const int k = e >> 8, u = e & 255;
            float s = 0.f;
            #pragma unroll
            for (int d = 0; d < 32; ++d) s += skeys[k * 32 + d] * Wv[u * 32 + d];
            svh[k * 256 + u] = s;
        }
        __syncthreads();
        for (int e = tid; e < 5 * 256; e += 256) {
            const int kp = e >> 8, u = e & 255;
            g_vhp[e] = mk2(svh[(2 * kp) * 256 + u], svh[(2 * kp + 1) * 256 + u]);
        }
        if (tid == 0) {
            int is64 = 1;
            for (int t = 1; t < 512; t += 2)
                if (pidx[t] != 0) { is64 = 0; break; }
            g_idx_is64 = is64;
        }
    }
}

// ---- staging (256 threads, 64x128 chunk) ----
__device__ __forceinline__ void ldg_chunk(
    const float* __restrict__ inputs, const float* __restrict__ ptab,
    const int* __restrict__ sIdx, int n, int base, int cc, int sl, int rq,
    float4* ra, float4* rb)
{
    const int sc = cc >> 1;
    const int col0 = (cc & 1) * 128 + sl * 4;
    const int nr = min(TILE, T_SEQ - base - sc * 64);
    #pragma unroll
    for (int m = 0; m < 8; ++m) {
        const int r = rq + m * 8;
        ra[m] = make_float4(0.f, 0.f, 0.f, 0.f);
        rb[m] = ra[m];
        if (r < nr) {
            ra[m] = *(const float4*)(inputs + (size_t)(n * T_SEQ + base + sc * 64 + r) * DQ + col0);
            rb[m] = *(const float4*)(ptab + (size_t)sIdx[sc * 64 + r] * DQ + col0);
        }
    }
}

__device__ __forceinline__ void sts_chunk(char* smem, int pbuf, int sl, int rq,
                                          const float4* ra, const float4* rb)
{
    #pragma unroll
    for (int m = 0; m < 8; ++m) {
        const int r = rq + m * 8;
        const float x0 = ra[m].x + rb[m].x, x1 = ra[m].y + rb[m].y;
        const float x2 = ra[m].z + rb[m].z, x3 = ra[m].w + rb[m].w;
        const uint h01 = packbf(x0, x1), h23 = packbf(x2, x3);
        const float2 f01 = bf2f(h01), f23 = bf2f(h23);
        const uint l01 = packbf(x0 - f01.x, x1 - f01.y);
        const uint l23 = packbf(x2 - f23.x, x3 - f23.y);
        *(uint4*)(smem + pbuf * XBYTES + r * 544 + sl * 16) = make_uint4(h01, l01, h23, l23);
    }
}

// =====================================================================
// Main kernel: warps = 2 row-halves (32 rows) x 4 n-splits (3/3/2/2);
// B fragments amortized over 2 row-groups -> half the B LDG traffic.
// =====================================================================
__global__ void __launch_bounds__(THREADS, 2)
attn_kernel(const float* __restrict__ inputs, const int* __restrict__ pidx,
            const float* __restrict__ ptab, float* __restrict__ out,
            float* __restrict__ scores)
{
    extern __shared__ char smem[];
    float* sLog = (float*)(smem + OFF_X1);     // aliases X buffer 1
    int*   sIdx = (int*)(smem + OFF_IDX);

    const int tid  = threadIdx.x;
    const int lane = tid & 31;
    const int w    = tid >> 5;          // 0..7
    const int rg2  = w & 1;             // row half: rows [32*rg2, +32)
    const int ns   = w >> 1;            // 0..3
    const int jt0  = (ns < 2) ? 3 * ns : (6 + 2 * (ns - 2));
    const int jcnt = (ns < 2) ? 3 : 2;
    const int gr   = lane >> 2, q = lane & 3;
    const int sl   = tid & 31, rq = tid >> 5;
    const int n    = blockIdx.y;
    const int base = blockIdx.x * 256;

    // ---- prologue: vhp, idx ----
    {
        uint4* vd = (uint4*)(smem + OFF_VH);
        const uint4* vs = (const uint4*)g_vhp;
        for (int e = tid; e < 5 * 256 / 2; e += THREADS) vd[e] = vs[e];
        const int is64 = g_idx_is64;
        const int t = base + tid;
        int v = 0;
        if (t < T_SEQ) {
            const int pos = n * T_SEQ + t;
            v = is64 ? pidx[2 * pos] : pidx[pos];
        }
        sIdx[tid] = v;
    }
    __syncthreads();

    // stage chunk 0
    {
        float4 ra[8], rb[8];
        ldg_chunk(inputs, ptab, sIdx, n, base, 0, sl, rq, ra, rb);
        sts_chunk(smem, 0, sl, rq, ra, rb);
    }
    __syncthreads();

    float acc[2][3][4];
    #pragma unroll
    for (int g = 0; g < 2; ++g)
        #pragma unroll
        for (int j = 0; j < 3; ++j)
            #pragma unroll
            for (int i = 0; i < 4; ++i) acc[g][j][i] = 0.f;

    #pragma unroll 2
    for (int c = 0; c < NC; ++c) {
        const int p = c & 1;
        const int sc = c >> 1;

        // A) LDGs for chunk c+1 (in flight under MMA)
        float4 ra[8], rb[8];
        if (c < NC - 1) ldg_chunk(inputs, ptab, sIdx, n, base, c + 1, sl, rq, ra, rb);

        // B) MMA chunk c: 32 rows (2 groups), jcnt n-tiles; B shared by groups
        {
            const uint2* xb = (const uint2*)(smem + p * XBYTES);
            #pragma unroll
            for (int ks = 0; ks < 8; ++ks) {
                const int gk = p * 8 + ks;
                uint2 A[2][4];
                #pragma unroll
                for (int g = 0; g < 2; ++g) {
                    const uint2* ap = xb + (rg2 * 32 + g * 16 + gr) * XSTR + ks * 8 + q;
                    A[g][0] = ap[0];
                    A[g][2] = ap[4];
                    A[g][1] = ap[8 * XSTR];
                    A[g][3] = ap[8 * XSTR + 4];
                }
                #pragma unroll
                for (int j = 0; j < 3; ++j) {
                    if (j < jcnt) {
                        const uint4 bf = __ldg(&g_Bf[((jt0 + j) * 16 + gk) * 32 + lane]);
                        #pragma unroll
                        for (int g = 0; g < 2; ++g) {
                            mma16816(acc[g][j], A[g][0].x, A[g][1].x, A[g][2].x, A[g][3].x, bf.x, bf.z);
                            mma16816(acc[g][j], A[g][0].x, A[g][1].x, A[g][2].x, A[g][3].x, bf.y, bf.w);
                            mma16816(acc[g][j], A[g][0].y, A[g][1].y, A[g][2].y, A[g][3].y, bf.x, bf.z);
                        }
                    }
                }
            }
        }
        __syncthreads();   // D: MMA reads of buf p complete; prior epilogue done

        // C) tile done: fragments -> sLog (paired stores)
        if (c & 1) {
            #pragma unroll
            for (int g = 0; g < 2; ++g) {
                const int r0 = rg2 * 32 + g * 16 + gr;
                #pragma unroll
                for (int j = 0; j < 3; ++j) {
                    if (j < jcnt) {
                        const int cc2 = (jt0 + j) * 8 + 2 * q;
                        *(float2*)(sLog + r0 * SLSTR + cc2)       = make_float2(acc[g][j][0], acc[g][j][1]);
                        *(float2*)(sLog + (r0 + 8) * SLSTR + cc2) = make_float2(acc[g][j][2], acc[g][j][3]);
                    }
                    #pragma unroll
                    for (int i = 0; i < 4; ++i) acc[g][j][i] = 0.f;
                }
            }
        }

        // E) store staged chunk c+1 into buffer p^1
        if (c < NC - 1) sts_chunk(smem, p ^ 1, sl, rq, ra, rb);

        if (c & 1) {
            const int nr = min(TILE, T_SEQ - base - sc * 64);
            __syncthreads();   // frags + sts visible
            // F1) softmax + scores: r = tid&63, heads h0 and h0+4
            {
                const int r = tid & 63;
                const int h0 = tid >> 6;        // 0..3
                #pragma unroll
                for (int hh = 0; hh < 2; ++hh) {
                    const int h = h0 + hh * 4;
                    float2* rowp = (float2*)(sLog + r * SLSTR + h * NTOK);
                    float lg[NTOK];
                    #pragma unroll
                    for (int kp = 0; kp < 5; ++kp) {
                        const float2 t2 = rowp[kp];
                        lg[2 * kp] = t2.x; lg[2 * kp + 1] = t2.y;
                    }
                    float mx = lg[0];
                    #pragma unroll
                    for (int k = 1; k < NTOK; ++k) mx = fmaxf(mx, lg[k]);
                    float s = 0.f, at[NTOK];
                    #pragma unroll
                    for (int k = 0; k < NTOK; ++k) { at[k] = __expf(lg[k] - mx); s += at[k]; }
                    const float inv = 1.0f / s;
                    #pragma unroll
                    for (int k = 0; k < NTOK; ++k) at[k] *= inv;
                    #pragma unroll
                    for (int kp = 0; kp < 5; ++kp)
                        rowp[kp] = make_float2(at[2 * kp], at[2 * kp + 1]);
                    if (r < nr) {
                        float* sp = scores + ((size_t)n * NJ + h * NTOK) * T_SEQ + base + sc * 64 + r;
                        #pragma unroll
                        for (int k = 0; k < NTOK; ++k) sp[(size_t)k * T_SEQ] = at[k];
                    }
                }
            }
            __syncthreads();   // attn visible
            // F2) out = attn @ vh, paired-k fma2
            {
                const int cb = tid & 63;        // cols [4cb, 4cb+4)
                const int rgq = tid >> 6;       // 0..3
                const int h = cb >> 3;
                const ull* vptr = (const ull*)(smem + OFF_VH);
                ull vv[5][4];
                #pragma unroll
                for (int kp = 0; kp < 5; ++kp) {
                    const ulonglong2 v01 = *(const ulonglong2*)(vptr + kp * 256 + cb * 4);
                    const ulonglong2 v23 = *(const ulonglong2*)(vptr + kp * 256 + cb * 4 + 2);
                    vv[kp][0] = v01.x; vv[kp][1] = v01.y;
                    vv[kp][2] = v23.x; vv[kp][3] = v23.y;
                }
                #pragma unroll 4
                for (int m = 0; m < 16; ++m) {
                    const int r = rgq + m * 4;
                    const ull* ar = (const ull*)(sLog + r * SLSTR + h * NTOK);
                    ull o0 = 0, o1 = 0, o2 = 0, o3 = 0;
                    #pragma unroll
                    for (int kp = 0; kp < 5; ++kp) {
                        const ull a2 = ar[kp];
                        fma2(o0, a2, vv[kp][0]);
                        fma2(o1, a2, vv[kp][1]);
                        fma2(o2, a2, vv[kp][2]);
                        fma2(o3, a2, vv[kp][3]);
                    }
                    if (r < nr) {
                        const float2 f0 = u2f2(o0), f1 = u2f2(o1);
                        const float2 f2 = u2f2(o2), f3 = u2f2(o3);
                        *(float4*)(out + (size_t)(n * T_SEQ + base + sc * 64 + r) * DQ + cb * 4) =
                            make_float4(f0.x + f0.y, f1.x + f1.y, f2.x + f2.y, f3.x + f3.y);
                    }
                }
            }
            // no trailing sync: next iteration's D covers the sLog hazard
        } else {
            __syncthreads();   // G: sts into buf1 visible before next MMA
        }
    }
}

extern "C" void kernel_launch(void* const* d_in, const int* in_sizes, int n_in,
                              void* d_out, int out_size) {
    const float* inputs = (const float*)d_in[0];
    const int*   pidx   = (const int*)d_in[1];
    const float* embed  = (const float*)d_in[2];
    const float* Wq     = (const float*)d_in[3];
    const float* Wk     = (const float*)d_in[4];
    const float* Wv     = (const float*)d_in[5];
    const float* ptab   = (const float*)d_in[6];

    float* out    = (float*)d_out;
    float* scores = (float*)d_out + OUT_ELEMS;

    cudaFuncSetAttribute(attn_kernel, cudaFuncAttributeMaxDynamicSharedMemorySize, SMEM_BYTES);

    precompute_kernel<<<NJ + 1, 256>>>(embed, Wq, Wk, Wv, pidx);
    attn_kernel<<<dim3(8, N_BATCH), THREADS, SMEM_BYTES>>>(inputs, pidx, ptab, out, scores);
}

// round 12
// speedup vs baseline: 1.1378x; 1.1378x over previous
#include <cuda_runtime.h>
#include <cuda_bf16.h>
#include <cstdint>

typedef unsigned long long ull;
typedef unsigned int uint;

#define N_BATCH 64
#define T_SEQ   2000
#define DQ      256
#define NTOK    10
#define NJ      80
#define NJT     10
#define TILE    64
#define N_ITEMS 2048         // 64 batches x 32 tiles
#define GRID_X  296          // 2 CTAs x 148 SMs, persistent-strided
#define THREADS 256
#define SCALE_LG 0.17677669529663687f
#define OUT_ELEMS (N_BATCH * T_SEQ * DQ)

// ---- smem (80,896 B/CTA -> 2 CTAs/SM) ----
#define XSTR   68            // uint2 per X row (544 B)
#define XBYTES 34816
#define OFF_X1 34816
#define OFF_VH 69632         // vhp: ull[5*256] = 10240 B
#define OFF_IDX 79872        // 2 x 64 ints (double-buffered)
#define SMEM_BYTES 80896
#define SLSTR  86            // sLog row stride (aliases X buf1)

__device__ uint4 g_Bf[NJT * 16 * 32];   // Wqk bf16 hi/lo in MMA fragment order
__device__ ull   g_vhp[5 * 256];        // vh k-pairs interleaved
__device__ int   g_idx_is64;

// ---------- helpers ----------
__device__ __forceinline__ void fma2(ull& acc, ull a, ull b) {
    asm("fma.rn.f32x2 %0, %1, %2, %0;" : "+l"(acc) : "l"(a), "l"(b));
}
__device__ __forceinline__ float2 u2f2(ull v) {
    float2 r; asm("mov.b64 {%0, %1}, %2;" : "=f"(r.x), "=f"(r.y) : "l"(v)); return r;
}
__device__ __forceinline__ ull mk2(float lo, float hi) {
    ull r; asm("mov.b64 %0, {%1, %2};" : "=l"(r) : "f"(lo), "f"(hi)); return r;
}
__device__ __forceinline__ uint packbf(float x0, float x1) {
    uint r; asm("cvt.rn.bf16x2.f32 %0, %1, %2;" : "=r"(r) : "f"(x1), "f"(x0)); return r;
}
__device__ __forceinline__ float2 bf2f(uint u) {
    __nv_bfloat162 h = *reinterpret_cast<__nv_bfloat162*>(&u);
    return __bfloat1622float2(h);
}
__device__ __forceinline__ void mma16816(float* c,
    uint a0, uint a1, uint a2, uint a3, uint b0, uint b1) {
    asm volatile("mma.sync.aligned.m16n8k16.row.col.f32.bf16.bf16.f32 "
        "{%0,%1,%2,%3}, {%4,%5,%6,%7}, {%8,%9}, {%0,%1,%2,%3};"
        : "+f"(c[0]), "+f"(c[1]), "+f"(c[2]), "+f"(c[3])
        : "r"(a0), "r"(a1), "r"(a2), "r"(a3), "r"(b0), "r"(b1));
}

// =====================================================================
// Precompute (unchanged): Wqk -> fragment-order bf16 hi/lo; vhp pairs.
// =====================================================================
__global__ void precompute_kernel(const float* __restrict__ embed,
                                  const float* __restrict__ Wq,
                                  const float* __restrict__ Wk,
                                  const float* __restrict__ Wv,
                                  const int*   __restrict__ pidx) {
    __shared__ float skeys[NTOK * 32];
    const int tid = threadIdx.x;
    for (int e = tid; e < NTOK * 32; e += 256) skeys[e] = tanhf(embed[e]);
    __syncthreads();

    const int b = blockIdx.x;
    if (b < NJ) {
        const int h = b / NTOK, k = b % NTOK;
        __shared__ float skm[32];
        if (tid < 32) {
            float s = 0.f;
            #pragma unroll
            for (int d = 0; d < 32; ++d) s += skeys[k * 32 + d] * Wk[(h * 32 + tid) * 32 + d];
            skm[tid] = s;
        }
        __syncthreads();
        if (tid < 128) {
            const int c0 = 2 * tid;
            float s0 = 0.f, s1 = 0.f;
            #pragma unroll
            for (int d = 0; d < 32; ++d) {
                const float km = skm[d];
                s0 += km * Wq[(h * 32 + d) * DQ + c0];
                s1 += km * Wq[(h * 32 + d) * DQ + c0 + 1];
            }
            s0 *= SCALE_LG; s1 *= SCALE_LG;
            const uint hi = packbf(s0, s1);
            const float2 f = bf2f(hi);
            const uint lo = packbf(s0 - f.x, s1 - f.y);
            const int j = b >> 3, gr = b & 7;
            const int gk = tid >> 3, qq = tid & 7;
            const int q = qq & 3, hf = qq >> 2;
            uint* dst = (uint*)&g_Bf[(j * 16 + gk) * 32 + gr * 4 + q];
            dst[hf * 2]     = hi;
            dst[hf * 2 + 1] = lo;
        }
    } else {
        __shared__ float svh[NTOK * 256];
        for (int e = tid; e < NTOK * DQ; e += 256) {
            const int k = e >> 8, u = e & 255;
            float s = 0.f;
            #pragma unroll
            for (int d = 0; d < 32; ++d) s += skeys[k * 32 + d] * Wv[u * 32 + d];
            svh[k * 256 + u] = s;
        }
        __syncthreads();
        for (int e = tid; e < 5 * 256; e += 256) {
            const int kp = e >> 8, u = e & 255;
            g_vhp[e] = mk2(svh[(2 * kp) * 256 + u], svh[(2 * kp + 1) * 256 + u]);
        }
        if (tid == 0) {
            int is64 = 1;
            for (int t = 1; t < 512; t += 2)
                if (pidx[t] != 0) { is64 = 0; break; }
            g_idx_is64 = is64;
        }
    }
}

// ---- staging (256 threads, 64 rows x 128 cols k-half) ----
__device__ __forceinline__ void ldg_chunk(
    const float* __restrict__ inputs, const float* __restrict__ ptab,
    const int* __restrict__ sIdxb, int n, int tbase, int half, int nr,
    int sl, int rq, float4* ra, float4* rb)
{
    const int col0 = half * 128 + sl * 4;
    #pragma unroll
    for (int m = 0; m < 8; ++m) {
        const int r = rq + m * 8;
        ra[m] = make_float4(0.f, 0.f, 0.f, 0.f);
        rb[m] = ra[m];
        if (r < nr) {
            ra[m] = *(const float4*)(inputs + (size_t)(n * T_SEQ + tbase + r) * DQ + col0);
            rb[m] = *(const float4*)(ptab + (size_t)sIdxb[r] * DQ + col0);
        }
    }
}

__device__ __forceinline__ void sts_chunk(char* smem, int pbuf, int sl, int rq,
                                          const float4* ra, const float4* rb)
{
    #pragma unroll
    for (int m = 0; m < 8; ++m) {
        const int r = rq + m * 8;
        const float x0 = ra[m].x + rb[m].x, x1 = ra[m].y + rb[m].y;
        const float x2 = ra[m].z + rb[m].z, x3 = ra[m].w + rb[m].w;
        const uint h01 = packbf(x0, x1), h23 = packbf(x2, x3);
        const float2 f01 = bf2f(h01), f23 = bf2f(h23);
        const uint l01 = packbf(x0 - f01.x, x1 - f01.y);
        const uint l23 = packbf(x2 - f23.x, x3 - f23.y);
        *(uint4*)(smem + pbuf * XBYTES + r * 544 + sl * 16) = make_uint4(h01, l01, h23, l23);
    }
}

// =====================================================================
// Main kernel: persistent 296 CTAs striding over 2048 single-tile items;
// continuous double-buffered chunk pipeline across items.
// =====================================================================
__global__ void __launch_bounds__(THREADS, 2)
attn_kernel(const float* __restrict__ inputs, const int* __restrict__ pidx,
            const float* __restrict__ ptab, float* __restrict__ out,
            float* __restrict__ scores)
{
    extern __shared__ char smem[];
    float* sLog = (float*)(smem + OFF_X1);     // aliases X buffer 1
    int*   sIdx = (int*)(smem + OFF_IDX);      // 2 x 64

    const int tid  = threadIdx.x;
    const int lane = tid & 31;
    const int w    = tid >> 5;          // 0..7
    const int rg4  = w & 3;
    const int jt0  = (w >> 2) * 5;      // n-split: n-tiles [jt0, jt0+5)
    const int gr   = lane >> 2, q = lane & 3;
    const int sl   = tid & 31, rq = tid >> 5;
    const int is64 = g_idx_is64;

    // ---- prologue: vhp, item0 idx ----
    {
        uint4* vd = (uint4*)(smem + OFF_VH);
        const uint4* vs = (const uint4*)g_vhp;
        for (int e = tid; e < 5 * 256 / 2; e += THREADS) vd[e] = vs[e];
        const int item0 = blockIdx.x;
        if (tid < 64) {
            const int n0 = item0 >> 5, tb0 = (item0 & 31) << 6;
            int v = 0;
            if (tb0 + tid < T_SEQ) {
                const int pos = n0 * T_SEQ + tb0 + tid;
                v = is64 ? pidx[2 * pos] : pidx[pos];
            }
            sIdx[tid] = v;
        }
    }
    __syncthreads();

    // stage item0 chunk half0 -> buf0
    {
        const int item0 = blockIdx.x;
        const int n0 = item0 >> 5, tb0 = (item0 & 31) << 6;
        const int nr0 = min(TILE, T_SEQ - tb0);
        float4 ra[8], rb[8];
        ldg_chunk(inputs, ptab, sIdx, n0, tb0, 0, nr0, sl, rq, ra, rb);
        sts_chunk(smem, 0, sl, rq, ra, rb);
    }
    __syncthreads();

    float acc[5][4];
    #pragma unroll
    for (int j = 0; j < 5; ++j)
        #pragma unroll
        for (int i = 0; i < 4; ++i) acc[j][i] = 0.f;

    int p = 0, ib = 0;
    #pragma unroll 1
    for (int item = blockIdx.x; item < N_ITEMS; item += GRID_X) {
        const int n = item >> 5, tbase = (item & 31) << 6;
        const int nr = min(TILE, T_SEQ - tbase);
        const int nxt = item + GRID_X;
        const int n2 = nxt >> 5, tb2 = (nxt & 31) << 6;

        // ================== chunk half 0 (buf p) ==================
        float4 ra[8], rb[8];
        // A: ldg this item's half1; gather next item's idx
        ldg_chunk(inputs, ptab, sIdx + ib * 64, n, tbase, 1, nr, sl, rq, ra, rb);
        if (nxt < N_ITEMS && tid < 64) {
            int v = 0;
            if (tb2 + tid < T_SEQ) {
                const int pos = n2 * T_SEQ + tb2 + tid;
                v = is64 ? pidx[2 * pos] : pidx[pos];
            }
            sIdx[(ib ^ 1) * 64 + tid] = v;
        }
        // B: MMA half0
        {
            const uint2* a0p = (const uint2*)(smem + p * XBYTES) + (rg4 * 16 + gr) * XSTR + q;
            const uint2* a1p = a0p + 8 * XSTR;
            #pragma unroll
            for (int ks = 0; ks < 8; ++ks) {
                const uint2 A0 = a0p[ks * 8];
                const uint2 A2 = a0p[ks * 8 + 4];
                const uint2 A1 = a1p[ks * 8];
                const uint2 A3 = a1p[ks * 8 + 4];
                #pragma unroll
                for (int j = 0; j < 5; ++j) {
                    const uint4 bf = __ldg(&g_Bf[((jt0 + j) * 16 + ks) * 32 + lane]);
                    mma16816(acc[j], A0.x, A1.x, A2.x, A3.x, bf.x, bf.z);
                    mma16816(acc[j], A0.x, A1.x, A2.x, A3.x, bf.y, bf.w);
                    mma16816(acc[j], A0.y, A1.y, A2.y, A3.y, bf.x, bf.z);
                }
            }
        }
        __syncthreads();   // D0
        sts_chunk(smem, p ^ 1, sl, rq, ra, rb);   // half1 -> buf p^1 (=buf1)
        __syncthreads();   // G0
        p ^= 1;

        // ================== chunk half 1 (buf p = buf1) ==================
        // A: ldg NEXT item's half0 (uses idx gathered above, visible via D0)
        if (nxt < N_ITEMS) {
            const int nrn = min(TILE, T_SEQ - tb2);
            ldg_chunk(inputs, ptab, sIdx + (ib ^ 1) * 64, n2, tb2, 0, nrn, sl, rq, ra, rb);
        }
        // B: MMA half1
        {
            const uint2* a0p = (const uint2*)(smem + p * XBYTES) + (rg4 * 16 + gr) * XSTR + q;
            const uint2* a1p = a0p + 8 * XSTR;
            #pragma unroll
            for (int ks = 0; ks < 8; ++ks) {
                const uint2 A0 = a0p[ks * 8];
                const uint2 A2 = a0p[ks * 8 + 4];
                const uint2 A1 = a1p[ks * 8];
                const uint2 A3 = a1p[ks * 8 + 4];
                #pragma unroll
                for (int j = 0; j < 5; ++j) {
                    const uint4 bf = __ldg(&g_Bf[((jt0 + j) * 16 + 8 + ks) * 32 + lane]);
                    mma16816(acc[j], A0.x, A1.x, A2.x, A3.x, bf.x, bf.z);
                    mma16816(acc[j], A0.x, A1.x, A2.x, A3.x, bf.y, bf.w);
                    mma16816(acc[j], A0.y, A1.y, A2.y, A3.y, bf.x, bf.z);
                }
            }
        }
        __syncthreads();   // D1: buf1 consumed; prior epilogue long done

        // C: fragments -> sLog (aliases buf1)
        {
            const int r0 = rg4 * 16 + gr;
            #pragma unroll
            for (int j = 0; j < 5; ++j) {
                const int cc2 = (jt0 + j) * 8 + 2 * q;
                *(float2*)(sLog + r0 * SLSTR + cc2)       = make_float2(acc[j][0], acc[j][1]);
                *(float2*)(sLog + (r0 + 8) * SLSTR + cc2) = make_float2(acc[j][2], acc[j][3]);
                #pragma unroll
                for (int i = 0; i < 4; ++i) acc[j][i] = 0.f;
            }
        }
        // E: next item's half0 -> buf p^1 (=buf0)
        if (nxt < N_ITEMS) sts_chunk(smem, p ^ 1, sl, rq, ra, rb);
        __syncthreads();   // frags + sts visible

        // F1: softmax + scores
        {
            const int r = tid & 63;
            const int h0 = tid >> 6;        // 0..3
            #pragma unroll
            for (int hh = 0; hh < 2; ++hh) {
                const int h = h0 + hh * 4;
                float2* rowp = (float2*)(sLog + r * SLSTR + h * NTOK);
                float lg[NTOK];
                #pragma unroll
                for (int kp = 0; kp < 5; ++kp) {
                    const float2 t2 = rowp[kp];
                    lg[2 * kp] = t2.x; lg[2 * kp + 1] = t2.y;
                }
                float mx = lg[0];
                #pragma unroll
                for (int k = 1; k < NTOK; ++k) mx = fmaxf(mx, lg[k]);
                float s = 0.f, at[NTOK];
                #pragma unroll
                for (int k = 0; k < NTOK; ++k) { at[k] = __expf(lg[k] - mx); s += at[k]; }
                const float inv = 1.0f / s;
                #pragma unroll
                for (int k = 0; k < NTOK; ++k) at[k] *= inv;
                #pragma unroll
                for (int kp = 0; kp < 5; ++kp)
                    rowp[kp] = make_float2(at[2 * kp], at[2 * kp + 1]);
                if (r < nr) {
                    float* sp = scores + ((size_t)n * NJ + h * NTOK) * T_SEQ + tbase + r;
                    #pragma unroll
                    for (int k = 0; k < NTOK; ++k) sp[(size_t)k * T_SEQ] = at[k];
                }
            }
        }
        __syncthreads();   // attn visible

        // F2: out = attn @ vh (paired-k fma2)
        {
            const int cb = tid & 63;        // cols [4cb, 4cb+4)
            const int rgq = tid >> 6;       // 0..3
            const int h = cb >> 3;
            const ull* vptr = (const ull*)(smem + OFF_VH);
            ull vv[5][4];
            #pragma unroll
            for (int kp = 0; kp < 5; ++kp) {
                const ulonglong2 v01 = *(const ulonglong2*)(vptr + kp * 256 + cb * 4);
                const ulonglong2 v23 = *(const ulonglong2*)(vptr + kp * 256 + cb * 4 + 2);
                vv[kp][0] = v01.x; vv[kp][1] = v01.y;
                vv[kp][2] = v23.x; vv[kp][3] = v23.y;
            }
            #pragma unroll 4
            for (int m = 0; m < 16; ++m) {
                const int r = rgq + m * 4;
                const ull* ar = (const ull*)(sLog + r * SLSTR + h * NTOK);
                ull o0 = 0, o1 = 0, o2 = 0, o3 = 0;
                #pragma unroll
                for (int kp = 0; kp < 5; ++kp) {
                    const ull a2 = ar[kp];
                    fma2(o0, a2, vv[kp][0]);
                    fma2(o1, a2, vv[kp][1]);
                    fma2(o2, a2, vv[kp][2]);
                    fma2(o3, a2, vv[kp][3]);
                }
                if (r < nr) {
                    const float2 f0 = u2f2(o0), f1 = u2f2(o1);
                    const float2 f2 = u2f2(o2), f3 = u2f2(o3);
                    *(float4*)(out + (size_t)(n * T_SEQ + tbase + r) * DQ + cb * 4) =
                        make_float4(f0.x + f0.y, f1.x + f1.y, f2.x + f2.y, f3.x + f3.y);
                }
            }
        }
        // no trailing sync: next item's D0 covers the sLog hazard
        p ^= 1;
        ib ^= 1;
    }
}

extern "C" void kernel_launch(void* const* d_in, const int* in_sizes, int n_in,
                              void* d_out, int out_size) {
    const float* inputs = (const float*)d_in[0];
    const int*   pidx   = (const int*)d_in[1];
    const float* embed  = (const float*)d_in[2];
    const float* Wq     = (const float*)d_in[3];
    const float* Wk     = (const float*)d_in[4];
    const float* Wv     = (const float*)d_in[5];
    const float* ptab   = (const float*)d_in[6];

    float* out    = (float*)d_out;
    float* scores = (float*)d_out + OUT_ELEMS;

    cudaFuncSetAttribute(attn_kernel, cudaFuncAttributeMaxDynamicSharedMemorySize, SMEM_BYTES);

    precompute_kernel<<<NJ + 1, 256>>>(embed, Wq, Wk, Wv, pidx);
    attn_kernel<<<GRID_X, THREADS, SMEM_BYTES>>>(inputs, pidx, ptab, out, scores);
}